// round 4
// baseline (speedup 1.0000x reference)
#include <cuda_runtime.h>
#include <cuda_bf16.h>
#include <math.h>
#include <stdint.h>

#define BB 4
#define CC 1024
#define DD 1024
#define HH 16
#define DHH 64
#define ROWS (BB*CC)              // 4096
#define ELEMS (BB*CC*DD)          // 4194304
#define ATTN_ELEMS (BB*HH*CC*CC)  // 67108864

// ---------------- scratch (__device__ globals; no allocation allowed) -------
__device__ float g_kn[ELEMS];
__device__ float g_vn[ELEMS];
__device__ float g_qp[ELEMS];
__device__ float g_kp[ELEMS];
__device__ float g_vp[ELEMS];
__device__ float g_ctx[ELEMS];
__device__ float g_proj[ELEMS];
__device__ float g_attn_scratch[ATTN_ELEMS];
__device__ __nv_bfloat16 g_ahi[ELEMS];
__device__ __nv_bfloat16 g_alo[ELEMS];
__device__ __nv_bfloat16 g_bhi[DD*DD];
__device__ __nv_bfloat16 g_blo[DD*DD];

// ---------------- helpers ---------------------------------------------------
__device__ __forceinline__ uint32_t smem_u32(const void* p) {
    uint32_t a;
    asm("{ .reg .u64 t; cvta.to.shared.u64 t, %1; cvt.u32.u64 %0, t; }"
        : "=r"(a) : "l"(p));
    return a;
}
__device__ __forceinline__ void ldmatrix_x4(uint32_t& r0, uint32_t& r1,
                                            uint32_t& r2, uint32_t& r3,
                                            uint32_t addr) {
    asm volatile("ldmatrix.sync.aligned.m8n8.x4.shared.b16 {%0,%1,%2,%3}, [%4];"
        : "=r"(r0), "=r"(r1), "=r"(r2), "=r"(r3) : "r"(addr));
}
__device__ __forceinline__ void mma_bf16(float* d, const uint32_t* a,
                                         uint32_t b0, uint32_t b1) {
    asm volatile(
        "mma.sync.aligned.m16n8k16.row.col.f32.bf16.bf16.f32 "
        "{%0,%1,%2,%3}, {%4,%5,%6,%7}, {%8,%9}, {%0,%1,%2,%3};"
        : "+f"(d[0]), "+f"(d[1]), "+f"(d[2]), "+f"(d[3])
        : "r"(a[0]), "r"(a[1]), "r"(a[2]), "r"(a[3]), "r"(b0), "r"(b1));
}

// ---------------------------------------------------------------------------
// HMMA GEMM: C[M,N] = A[M,K] @ B^T + bias,  A=[M,K], B=[N,K] (both K-major),
// bf16 hi/lo 3-MMA split for ~fp32 precision. Block tile 128x128, BK=32.
// 256 threads = 8 warps in 2x4; warp tile 64x32.
// ---------------------------------------------------------------------------
#define GPAD 40   // smem row stride in bf16 (80B = 5*16B, conflict-free ldmatrix)

__global__ __launch_bounds__(256) void mma_gemm_kernel(
    const __nv_bfloat16* __restrict__ Ahi, const __nv_bfloat16* __restrict__ Alo,
    const __nv_bfloat16* __restrict__ Bhi, const __nv_bfloat16* __restrict__ Blo,
    const float* __restrict__ bias, float* __restrict__ Cm,
    int Mtot, int Ntot, int Ktot)
{
    __shared__ __nv_bfloat16 sAh[128 * GPAD];
    __shared__ __nv_bfloat16 sAl[128 * GPAD];
    __shared__ __nv_bfloat16 sBh[128 * GPAD];
    __shared__ __nv_bfloat16 sBl[128 * GPAD];

    int tid = threadIdx.x, wid = tid >> 5, lane = tid & 31;
    int m0 = blockIdx.y * 128, n0 = blockIdx.x * 128;
    int wm = (wid >> 2) * 64;      // warp m offset (0 or 64)
    int wn = (wid & 3) * 32;       // warp n offset (0,32,64,96)

    float acc[4][4][4];            // [mtile][ntile][frag]
    #pragma unroll
    for (int i = 0; i < 4; i++)
        #pragma unroll
        for (int j = 0; j < 4; j++)
            #pragma unroll
            for (int q = 0; q < 4; q++) acc[i][j][q] = 0.f;

    // precomputed ldmatrix smem addresses (element offsets -> bytes)
    uint32_t aAh = smem_u32(sAh), aAl = smem_u32(sAl);
    uint32_t aBh = smem_u32(sBh), aBl = smem_u32(sBl);
    int a_row = (lane & 15), a_k8 = (lane >> 4);          // A: row, k-half
    int b_n  = (lane >> 4) * 8 + (lane & 7);              // B: n within 16
    int b_k8 = (lane >> 3) & 1;                           // B: k-half

    for (int kt = 0; kt < Ktot; kt += 32) {
        // gmem -> regs
        uint4 ra[2], rl[2], rb[2], rc[2];
        #pragma unroll
        for (int i = 0; i < 2; i++) {
            int idx = tid + i * 256;          // 0..511
            int row = idx >> 2, c = idx & 3;  // c = 16B unit (8 bf16)
            size_t ga = (size_t)(m0 + row) * Ktot + kt + c * 8;
            size_t gb = (size_t)(n0 + row) * Ktot + kt + c * 8;
            ra[i] = *(const uint4*)(Ahi + ga);
            rl[i] = *(const uint4*)(Alo + ga);
            rb[i] = *(const uint4*)(Bhi + gb);
            rc[i] = *(const uint4*)(Blo + gb);
        }
        __syncthreads();   // previous compute done
        #pragma unroll
        for (int i = 0; i < 2; i++) {
            int idx = tid + i * 256;
            int row = idx >> 2, c = idx & 3;
            int so = row * GPAD + c * 8;
            *(uint4*)(sAh + so) = ra[i];
            *(uint4*)(sAl + so) = rl[i];
            *(uint4*)(sBh + so) = rb[i];
            *(uint4*)(sBl + so) = rc[i];
        }
        __syncthreads();

        #pragma unroll
        for (int kk = 0; kk < 32; kk += 16) {
            // A fragments: 4 m-tiles, hi & lo
            uint32_t ah[4][4], al[4][4];
            #pragma unroll
            for (int mt = 0; mt < 4; mt++) {
                uint32_t off = (uint32_t)((wm + mt * 16 + a_row) * GPAD
                                          + kk + a_k8 * 8) * 2;
                ldmatrix_x4(ah[mt][0], ah[mt][1], ah[mt][2], ah[mt][3], aAh + off);
                ldmatrix_x4(al[mt][0], al[mt][1], al[mt][2], al[mt][3], aAl + off);
            }
            // B fragments: 2 x4-loads cover n 0-15 / 16-31, hi & lo
            uint32_t bh[2][4], bl[2][4];
            #pragma unroll
            for (int bt = 0; bt < 2; bt++) {
                uint32_t off = (uint32_t)((wn + bt * 16 + b_n) * GPAD
                                          + kk + b_k8 * 8) * 2;
                ldmatrix_x4(bh[bt][0], bh[bt][1], bh[bt][2], bh[bt][3], aBh + off);
                ldmatrix_x4(bl[bt][0], bl[bt][1], bl[bt][2], bl[bt][3], aBl + off);
            }
            #pragma unroll
            for (int mt = 0; mt < 4; mt++) {
                #pragma unroll
                for (int nt = 0; nt < 4; nt++) {
                    int bt = nt >> 1, hf = (nt & 1) * 2;
                    mma_bf16(acc[mt][nt], ah[mt], bh[bt][hf], bh[bt][hf + 1]); // hi*hi
                    mma_bf16(acc[mt][nt], ah[mt], bl[bt][hf], bl[bt][hf + 1]); // hi*lo
                    mma_bf16(acc[mt][nt], al[mt], bh[bt][hf], bh[bt][hf + 1]); // lo*hi
                }
            }
        }
    }

    // epilogue + bias
    int gr = lane >> 2, gc2 = (lane & 3) * 2;
    #pragma unroll
    for (int mt = 0; mt < 4; mt++) {
        int r = m0 + wm + mt * 16 + gr;
        #pragma unroll
        for (int nt = 0; nt < 4; nt++) {
            int c = n0 + wn + nt * 8 + gc2;
            float2 b2 = *(const float2*)(bias + c);
            float2 o0, o1;
            o0.x = acc[mt][nt][0] + b2.x; o0.y = acc[mt][nt][1] + b2.y;
            o1.x = acc[mt][nt][2] + b2.x; o1.y = acc[mt][nt][3] + b2.y;
            *(float2*)(Cm + (size_t)r * Ntot + c) = o0;
            *(float2*)(Cm + (size_t)(r + 8) * Ntot + c) = o1;
        }
    }
}

// ---------------------------------------------------------------------------
// fp32 -> bf16 hi/lo split (elementwise)
// ---------------------------------------------------------------------------
__global__ __launch_bounds__(256) void split_kernel(
    const float* __restrict__ x, __nv_bfloat16* __restrict__ hi,
    __nv_bfloat16* __restrict__ lo)
{
    int i = blockIdx.x * 256 + threadIdx.x;     // float4 index
    float4 v = ((const float4*)x)[i];
    __nv_bfloat16 h0 = __float2bfloat16(v.x), h1 = __float2bfloat16(v.y);
    __nv_bfloat16 h2 = __float2bfloat16(v.z), h3 = __float2bfloat16(v.w);
    __nv_bfloat16 l0 = __float2bfloat16(v.x - __bfloat162float(h0));
    __nv_bfloat16 l1 = __float2bfloat16(v.y - __bfloat162float(h1));
    __nv_bfloat16 l2 = __float2bfloat16(v.z - __bfloat162float(h2));
    __nv_bfloat16 l3 = __float2bfloat16(v.w - __bfloat162float(h3));
    union { __nv_bfloat162 b[2]; uint2 u; } ph, pl;
    ph.b[0] = __halves2bfloat162(h0, h1); ph.b[1] = __halves2bfloat162(h2, h3);
    pl.b[0] = __halves2bfloat162(l0, l1); pl.b[1] = __halves2bfloat162(l2, l3);
    ((uint2*)hi)[i] = ph.u;
    ((uint2*)lo)[i] = pl.u;
}

// W[K,N] -> hiT/loT [N,K] bf16 (transposed split, smem tiled)
__global__ void split_wt_kernel(const float* __restrict__ W,
                                __nv_bfloat16* __restrict__ hiT,
                                __nv_bfloat16* __restrict__ loT)
{
    __shared__ float t[32][33];
    int k0 = blockIdx.y * 32, n0 = blockIdx.x * 32;
    int tx = threadIdx.x, ty = threadIdx.y;   // 32 x 8
    #pragma unroll
    for (int j = 0; j < 4; j++)
        t[ty + j * 8][tx] = W[(size_t)(k0 + ty + j * 8) * DD + n0 + tx];
    __syncthreads();
    #pragma unroll
    for (int j = 0; j < 4; j++) {
        float x = t[tx][ty + j * 8];
        __nv_bfloat16 h = __float2bfloat16(x);
        __nv_bfloat16 l = __float2bfloat16(x - __bfloat162float(h));
        size_t o = (size_t)(n0 + ty + j * 8) * DD + k0 + tx;
        hiT[o] = h;
        loT[o] = l;
    }
}

// ---------------------------------------------------------------------------
// LayerNorm (one block per row)
// ---------------------------------------------------------------------------
__global__ __launch_bounds__(256) void ln_kernel(
    const float* __restrict__ x, const float* __restrict__ gam,
    const float* __restrict__ bet, float* __restrict__ y)
{
    int row = blockIdx.x;
    int tid = threadIdx.x;
    const float4 v = ((const float4*)(x + (size_t)row * DD))[tid];
    float s  = v.x + v.y + v.z + v.w;
    float ss = v.x*v.x + v.y*v.y + v.z*v.z + v.w*v.w;
    #pragma unroll
    for (int o = 16; o > 0; o >>= 1) {
        s  += __shfl_xor_sync(0xFFFFFFFFu, s, o);
        ss += __shfl_xor_sync(0xFFFFFFFFu, ss, o);
    }
    __shared__ float sh_s[8], sh_ss[8];
    __shared__ float sh_m, sh_r;
    int w = tid >> 5, l = tid & 31;
    if (l == 0) { sh_s[w] = s; sh_ss[w] = ss; }
    __syncthreads();
    if (tid == 0) {
        float S = 0.f, SS = 0.f;
        #pragma unroll
        for (int i = 0; i < 8; i++) { S += sh_s[i]; SS += sh_ss[i]; }
        float m = S * (1.0f / DD);
        float var = SS * (1.0f / DD) - m * m;
        sh_m = m;
        sh_r = rsqrtf(var + 1e-5f);
    }
    __syncthreads();
    float m = sh_m, r = sh_r;
    const float4 g4 = ((const float4*)gam)[tid];
    const float4 b4 = ((const float4*)bet)[tid];
    float4 o;
    o.x = (v.x - m) * r * g4.x + b4.x;
    o.y = (v.y - m) * r * g4.y + b4.y;
    o.z = (v.z - m) * r * g4.z + b4.z;
    o.w = (v.w - m) * r * g4.w + b4.w;
    ((float4*)(y + (size_t)row * DD))[tid] = o;
}

// ---------------------------------------------------------------------------
// Scores per head (fp32 FFMA, K=64) -> attn buffer
// ---------------------------------------------------------------------------
#define BM 64
#define BN 64
#define BK 16
__global__ __launch_bounds__(256) void scores_kernel(
    const float* __restrict__ qp, const float* __restrict__ kp,
    float* __restrict__ attn)
{
    int bh = blockIdx.z;
    int b = bh >> 4, h = bh & 15;
    const float* A  = qp + (size_t)b * CC * DD + h * DHH;
    const float* Bp = kp + (size_t)b * CC * DD + h * DHH;
    float* Cp = attn + (size_t)bh * CC * CC;

    __shared__ float As[BK][BM + 4];
    __shared__ float Bs[BK][BN + 4];
    int tid = threadIdx.x;
    int tx = tid & 15, ty = tid >> 4;
    int m0 = blockIdx.y * BM, n0 = blockIdx.x * BN;
    float acc[4][4] = {};
    for (int kt = 0; kt < DHH; kt += BK) {
        #pragma unroll
        for (int i = 0; i < 4; i++) {
            int idx = tid + i * 256;
            int m = idx >> 4, kk = idx & 15;
            As[kk][m] = A [(size_t)(m0 + m) * DD + kt + kk];
            Bs[kk][m] = Bp[(size_t)(n0 + m) * DD + kt + kk];
        }
        __syncthreads();
        #pragma unroll
        for (int kk = 0; kk < BK; kk++) {
            float a[4], bb[4];
            #pragma unroll
            for (int i = 0; i < 4; i++) a[i]  = As[kk][ty * 4 + i];
            #pragma unroll
            for (int j = 0; j < 4; j++) bb[j] = Bs[kk][tx * 4 + j];
            #pragma unroll
            for (int i = 0; i < 4; i++)
                #pragma unroll
                for (int j = 0; j < 4; j++)
                    acc[i][j] += a[i] * bb[j];
        }
        __syncthreads();
    }
    #pragma unroll
    for (int i = 0; i < 4; i++)
        #pragma unroll
        for (int j = 0; j < 4; j++)
            Cp[(size_t)(m0 + ty * 4 + i) * CC + n0 + tx * 4 + j] = acc[i][j];
}

// ---------------------------------------------------------------------------
// GELU*scale + softmax (in place)
// ---------------------------------------------------------------------------
__global__ __launch_bounds__(256) void softmax_kernel(float* __restrict__ attn)
{
    size_t row = blockIdx.x;
    float* r = attn + row * (size_t)CC;
    int tid = threadIdx.x;
    float4 v = ((float4*)r)[tid];
    const float scale = 0.125f;
    const float inv_sqrt2 = 0.70710678118654752f;
    float t0 = 0.5f * v.x * (1.0f + erff(v.x * inv_sqrt2)) * scale;
    float t1 = 0.5f * v.y * (1.0f + erff(v.y * inv_sqrt2)) * scale;
    float t2 = 0.5f * v.z * (1.0f + erff(v.z * inv_sqrt2)) * scale;
    float t3 = 0.5f * v.w * (1.0f + erff(v.w * inv_sqrt2)) * scale;

    float mx = fmaxf(fmaxf(t0, t1), fmaxf(t2, t3));
    #pragma unroll
    for (int o = 16; o > 0; o >>= 1)
        mx = fmaxf(mx, __shfl_xor_sync(0xFFFFFFFFu, mx, o));
    __shared__ float shm[8];
    __shared__ float shv;
    int w = tid >> 5, l = tid & 31;
    if (l == 0) shm[w] = mx;
    __syncthreads();
    if (tid == 0) {
        float M = shm[0];
        #pragma unroll
        for (int i = 1; i < 8; i++) M = fmaxf(M, shm[i]);
        shv = M;
    }
    __syncthreads();
    float M = shv;
    float e0 = __expf(t0 - M), e1 = __expf(t1 - M);
    float e2 = __expf(t2 - M), e3 = __expf(t3 - M);
    float s = e0 + e1 + e2 + e3;
    #pragma unroll
    for (int o = 16; o > 0; o >>= 1)
        s += __shfl_xor_sync(0xFFFFFFFFu, s, o);
    if (l == 0) shm[w] = s;
    __syncthreads();
    if (tid == 0) {
        float S = 0.f;
        #pragma unroll
        for (int i = 0; i < 8; i++) S += shm[i];
        shv = 1.0f / S;
    }
    __syncthreads();
    float inv = shv;
    float4 o;
    o.x = e0 * inv; o.y = e1 * inv; o.z = e2 * inv; o.w = e3 * inv;
    ((float4*)r)[tid] = o;
}

// ---------------------------------------------------------------------------
// ctx = attn @ V per head (fp32 FFMA)
// ---------------------------------------------------------------------------
__global__ __launch_bounds__(256) void ctx_kernel(
    const float* __restrict__ attn, const float* __restrict__ vp,
    float* __restrict__ ctx)
{
    int bh = blockIdx.z;
    int b = bh >> 4, h = bh & 15;
    const float* A  = attn + (size_t)bh * CC * CC;
    const float* Bp = vp  + (size_t)b * CC * DD + h * DHH;
    float*       Cp = ctx + (size_t)b * CC * DD + h * DHH;

    __shared__ float As[BK][BM + 4];
    __shared__ float Bs[BK][BN + 4];
    int tid = threadIdx.x;
    int tx = tid & 15, ty = tid >> 4;
    int m0 = blockIdx.y * BM;
    float acc[4][4] = {};
    for (int kt = 0; kt < CC; kt += BK) {
        #pragma unroll
        for (int i = 0; i < 4; i++) {
            int idx = tid + i * 256;
            int m = idx >> 4, kk = idx & 15;
            As[kk][m] = A[(size_t)(m0 + m) * CC + kt + kk];
        }
        #pragma unroll
        for (int i = 0; i < 4; i++) {
            int idx = tid + i * 256;
            int kk = idx >> 6, n = idx & 63;
            Bs[kk][n] = Bp[(size_t)(kt + kk) * DD + n];
        }
        __syncthreads();
        #pragma unroll
        for (int kk = 0; kk < BK; kk++) {
            float a[4], bb[4];
            #pragma unroll
            for (int i = 0; i < 4; i++) a[i]  = As[kk][ty * 4 + i];
            #pragma unroll
            for (int j = 0; j < 4; j++) bb[j] = Bs[kk][tx * 4 + j];
            #pragma unroll
            for (int i = 0; i < 4; i++)
                #pragma unroll
                for (int j = 0; j < 4; j++)
                    acc[i][j] += a[i] * bb[j];
        }
        __syncthreads();
    }
    #pragma unroll
    for (int i = 0; i < 4; i++)
        #pragma unroll
        for (int j = 0; j < 4; j++)
            Cp[(size_t)(m0 + ty * 4 + i) * DD + tx * 4 + j] = acc[i][j];
}

// ---------------------------------------------------------------------------
// L2 normalize rows
// ---------------------------------------------------------------------------
__global__ __launch_bounds__(256) void l2norm_kernel(
    const float* __restrict__ x, float* __restrict__ y)
{
    int row = blockIdx.x;
    int tid = threadIdx.x;
    const float4 v = ((const float4*)(x + (size_t)row * DD))[tid];
    float ss = v.x*v.x + v.y*v.y + v.z*v.z + v.w*v.w;
    #pragma unroll
    for (int o = 16; o > 0; o >>= 1)
        ss += __shfl_xor_sync(0xFFFFFFFFu, ss, o);
    __shared__ float sh[8];
    __shared__ float shinv;
    int w = tid >> 5, l = tid & 31;
    if (l == 0) sh[w] = ss;
    __syncthreads();
    if (tid == 0) {
        float S = 0.f;
        #pragma unroll
        for (int i = 0; i < 8; i++) S += sh[i];
        shinv = 1.0f / fmaxf(sqrtf(S), 1e-12f);
    }
    __syncthreads();
    float inv = shinv;
    float4 o;
    o.x = v.x * inv; o.y = v.y * inv; o.z = v.z * inv; o.w = v.w * inv;
    ((float4*)(y + (size_t)row * DD))[tid] = o;
}

// ---------------------------------------------------------------------------
extern "C" void kernel_launch(void* const* d_in, const int* in_sizes, int n_in,
                              void* d_out, int out_size)
{
    const float* q      = (const float*)d_in[0];
    const float* k      = (const float*)d_in[1];
    const float* v      = (const float*)d_in[2];
    const float* ln_k_g = (const float*)d_in[3];
    const float* ln_k_b = (const float*)d_in[4];
    const float* ln_v_g = (const float*)d_in[5];
    const float* ln_v_b = (const float*)d_in[6];
    const float* Wq     = (const float*)d_in[7];
    const float* bq     = (const float*)d_in[8];
    const float* Wk     = (const float*)d_in[9];
    const float* bk     = (const float*)d_in[10];
    const float* Wv     = (const float*)d_in[11];
    const float* bv     = (const float*)d_in[12];
    const float* Wo     = (const float*)d_in[13];
    const float* bo     = (const float*)d_in[14];

    float* out = (float*)d_out;

    float *kn, *vn, *qp, *kp, *vp, *ctx, *proj, *attn_scr;
    __nv_bfloat16 *ahi, *alo, *bhi, *blo;
    cudaGetSymbolAddress((void**)&kn,   g_kn);
    cudaGetSymbolAddress((void**)&vn,   g_vn);
    cudaGetSymbolAddress((void**)&qp,   g_qp);
    cudaGetSymbolAddress((void**)&kp,   g_kp);
    cudaGetSymbolAddress((void**)&vp,   g_vp);
    cudaGetSymbolAddress((void**)&ctx,  g_ctx);
    cudaGetSymbolAddress((void**)&proj, g_proj);
    cudaGetSymbolAddress((void**)&attn_scr, g_attn_scratch);
    cudaGetSymbolAddress((void**)&ahi, g_ahi);
    cudaGetSymbolAddress((void**)&alo, g_alo);
    cudaGetSymbolAddress((void**)&bhi, g_bhi);
    cudaGetSymbolAddress((void**)&blo, g_blo);

    float* attn = (out_size >= (int)(ELEMS + ATTN_ELEMS)) ? (out + (size_t)ELEMS)
                                                          : attn_scr;

    dim3 gmm(DD / 128, ROWS / 128);      // (8, 32)
    dim3 gwt(DD / 32, DD / 32);          // (32, 32)
    dim3 bwt(32, 8);
    int splitBlocks = ELEMS / 4 / 256;   // 4096

    // 1) LayerNorm k, v
    ln_kernel<<<ROWS, 256>>>(k, ln_k_g, ln_k_b, kn);
    ln_kernel<<<ROWS, 256>>>(v, ln_v_g, ln_v_b, vn);

    // 2) q projection
    split_kernel<<<splitBlocks, 256>>>(q, ahi, alo);
    split_wt_kernel<<<gwt, bwt>>>(Wq, bhi, blo);
    mma_gemm_kernel<<<gmm, 256>>>(ahi, alo, bhi, blo, bq, qp, ROWS, DD, DD);

    // 3) k projection
    split_kernel<<<splitBlocks, 256>>>(kn, ahi, alo);
    split_wt_kernel<<<gwt, bwt>>>(Wk, bhi, blo);
    mma_gemm_kernel<<<gmm, 256>>>(ahi, alo, bhi, blo, bk, kp, ROWS, DD, DD);

    // 4) v projection
    split_kernel<<<splitBlocks, 256>>>(vn, ahi, alo);
    split_wt_kernel<<<gwt, bwt>>>(Wv, bhi, blo);
    mma_gemm_kernel<<<gmm, 256>>>(ahi, alo, bhi, blo, bv, vp, ROWS, DD, DD);

    // 5) attention
    scores_kernel<<<dim3(CC / BN, CC / BM, BB * HH), 256>>>(qp, kp, attn);
    softmax_kernel<<<BB * HH * CC, 256>>>(attn);
    ctx_kernel<<<dim3(1, CC / BM, BB * HH), 256>>>(attn, vp, ctx);

    // 6) output projection + L2 normalize
    split_kernel<<<splitBlocks, 256>>>(ctx, ahi, alo);
    split_wt_kernel<<<gwt, bwt>>>(Wo, bhi, blo);
    mma_gemm_kernel<<<gmm, 256>>>(ahi, alo, bhi, blo, bo, proj, ROWS, DD, DD);
    l2norm_kernel<<<ROWS, 256>>>(proj, out);
}

// round 5
// speedup vs baseline: 2.5187x; 2.5187x over previous
#include <cuda_runtime.h>
#include <cuda_bf16.h>
#include <math.h>
#include <stdint.h>

#define BB 4
#define CC 1024
#define DD 1024
#define HH 16
#define DHH 64
#define ROWS (BB*CC)              // 4096
#define ELEMS (BB*CC*DD)          // 4194304
#define ATTN_ELEMS (BB*HH*CC*CC)  // 67108864

typedef __nv_bfloat16 bf;

// ---------------- scratch (__device__ globals; no allocation allowed) -------
__device__ float g_vp[ELEMS];            // v projection (fp32, pre-transpose)
__device__ float g_proj[ELEMS];          // final projection before l2norm
__device__ float g_attn_scratch[ATTN_ELEMS];
__device__ bf g_qh[ELEMS],  g_ql[ELEMS];     // q split (A of q-proj)
__device__ bf g_knh[ELEMS], g_knl[ELEMS];    // LN(k) hi/lo
__device__ bf g_vnh[ELEMS], g_vnl[ELEMS];    // LN(v) hi/lo
__device__ bf g_qph[ELEMS], g_qpl[ELEMS];    // q-proj out hi/lo
__device__ bf g_kph[ELEMS], g_kpl[ELEMS];    // k-proj out hi/lo
__device__ bf g_vth[ELEMS], g_vtl[ELEMS];    // vp transposed per batch [b][n][c]
__device__ bf g_cxh[ELEMS], g_cxl[ELEMS];    // ctx hi/lo
__device__ bf g_bhi[DD*DD], g_blo[DD*DD];    // weight split (reused)
__device__ bf g_ath[ATTN_ELEMS], g_atl[ATTN_ELEMS]; // attn hi/lo

// ---------------- PTX helpers ----------------------------------------------
__device__ __forceinline__ uint32_t smem_u32(const void* p) {
    uint32_t a;
    asm("{ .reg .u64 t; cvta.to.shared.u64 t, %1; cvt.u32.u64 %0, t; }"
        : "=r"(a) : "l"(p));
    return a;
}
__device__ __forceinline__ void ldmatrix_x4(uint32_t& r0, uint32_t& r1,
                                            uint32_t& r2, uint32_t& r3,
                                            uint32_t addr) {
    asm volatile("ldmatrix.sync.aligned.m8n8.x4.shared.b16 {%0,%1,%2,%3}, [%4];"
        : "=r"(r0), "=r"(r1), "=r"(r2), "=r"(r3) : "r"(addr));
}
__device__ __forceinline__ void mma_bf16(float* d, const uint32_t* a,
                                         uint32_t b0, uint32_t b1) {
    asm volatile(
        "mma.sync.aligned.m16n8k16.row.col.f32.bf16.bf16.f32 "
        "{%0,%1,%2,%3}, {%4,%5,%6,%7}, {%8,%9}, {%0,%1,%2,%3};"
        : "+f"(d[0]), "+f"(d[1]), "+f"(d[2]), "+f"(d[3])
        : "r"(a[0]), "r"(a[1]), "r"(a[2]), "r"(a[3]), "r"(b0), "r"(b1));
}
#define CP16(dst, src) \
    asm volatile("cp.async.cg.shared.global [%0], [%1], 16;" \
        :: "r"((uint32_t)(dst)), "l"(src))
#define CP_COMMIT() asm volatile("cp.async.commit_group;" ::: "memory")
#define CP_WAIT0()  asm volatile("cp.async.wait_group 0;" ::: "memory")
#define CP_WAIT1()  asm volatile("cp.async.wait_group 1;" ::: "memory")

// ---------------------------------------------------------------------------
// Generic 128x128 HMMA core: C = A[M,K] @ B^T + bias, A/B hi-lo bf16 K-major.
// 256 threads = 8 warps (2x4), warp tile 64x32, BK=32, cp.async 2-stage.
// Optional outputs: fp32 C and/or bf16 hi/lo C.
// ---------------------------------------------------------------------------
#define GP 40               // smem row stride (bf16) = 80B, conflict-free
#define STG 40960           // stage bytes: 4 arrays x 128*GP*2
#define AHOF 0
#define ALOF 10240
#define BHOF 20480
#define BLOF 30720

__device__ __forceinline__ void hgemm128_core(
    uint32_t sb,
    const bf* __restrict__ Ahi, const bf* __restrict__ Alo, int lda,
    const bf* __restrict__ Bhi, const bf* __restrict__ Blo, int ldb,
    const float* __restrict__ bias,
    float* __restrict__ Cf, int ldcf,
    bf* __restrict__ Chi, bf* __restrict__ Clo, int ldch,
    int Ktot, int m0, int n0)
{
    int tid = threadIdx.x, wid = tid >> 5, lane = tid & 31;
    int wm = (wid >> 2) * 64, wn = (wid & 3) * 32;
    float acc[4][4][4];
    #pragma unroll
    for (int i = 0; i < 4; i++)
        #pragma unroll
        for (int j = 0; j < 4; j++)
            #pragma unroll
            for (int q = 0; q < 4; q++) acc[i][j][q] = 0.f;

    int a_row = lane & 15, a_k8 = lane >> 4;
    int b_n = (lane >> 4) * 8 + (lane & 7), b_k8 = (lane >> 3) & 1;
    int r0 = tid >> 2, c0 = tid & 3;

    auto do_load = [&](int kt, int s) {
        uint32_t base = sb + s * STG;
        #pragma unroll
        for (int i = 0; i < 2; i++) {
            int row = r0 + i * 64;
            uint32_t so = (uint32_t)(row * GP + c0 * 8) * 2;
            size_t ga = (size_t)(m0 + row) * lda + kt * 32 + c0 * 8;
            size_t gb = (size_t)(n0 + row) * ldb + kt * 32 + c0 * 8;
            CP16(base + AHOF + so, Ahi + ga);
            CP16(base + ALOF + so, Alo + ga);
            CP16(base + BHOF + so, Bhi + gb);
            CP16(base + BLOF + so, Blo + gb);
        }
    };
    auto do_compute = [&](int s) {
        uint32_t base = sb + s * STG;
        #pragma unroll
        for (int kk = 0; kk < 32; kk += 16) {
            uint32_t ah[4][4], al[4][4], bh[2][4], bl[2][4];
            #pragma unroll
            for (int mt = 0; mt < 4; mt++) {
                uint32_t off = (uint32_t)((wm + mt * 16 + a_row) * GP
                                          + kk + a_k8 * 8) * 2;
                ldmatrix_x4(ah[mt][0], ah[mt][1], ah[mt][2], ah[mt][3],
                            base + AHOF + off);
                ldmatrix_x4(al[mt][0], al[mt][1], al[mt][2], al[mt][3],
                            base + ALOF + off);
            }
            #pragma unroll
            for (int bt = 0; bt < 2; bt++) {
                uint32_t off = (uint32_t)((wn + bt * 16 + b_n) * GP
                                          + kk + b_k8 * 8) * 2;
                ldmatrix_x4(bh[bt][0], bh[bt][1], bh[bt][2], bh[bt][3],
                            base + BHOF + off);
                ldmatrix_x4(bl[bt][0], bl[bt][1], bl[bt][2], bl[bt][3],
                            base + BLOF + off);
            }
            #pragma unroll
            for (int mt = 0; mt < 4; mt++) {
                #pragma unroll
                for (int nt = 0; nt < 4; nt++) {
                    int bt = nt >> 1, hf = (nt & 1) * 2;
                    mma_bf16(acc[mt][nt], ah[mt], bh[bt][hf], bh[bt][hf + 1]);
                    mma_bf16(acc[mt][nt], ah[mt], bl[bt][hf], bl[bt][hf + 1]);
                    mma_bf16(acc[mt][nt], al[mt], bh[bt][hf], bh[bt][hf + 1]);
                }
            }
        }
    };

    int nch = Ktot / 32;
    do_load(0, 0); CP_COMMIT();
    for (int kt = 0; kt < nch; kt++) {
        int cur = kt & 1;
        if (kt + 1 < nch) { do_load(kt + 1, cur ^ 1); CP_COMMIT(); CP_WAIT1(); }
        else              { CP_WAIT0(); }
        __syncthreads();
        do_compute(cur);
        __syncthreads();
    }

    int gr = lane >> 2, gc2 = (lane & 3) * 2;
    #pragma unroll
    for (int mt = 0; mt < 4; mt++) {
        int r = m0 + wm + mt * 16 + gr;
        #pragma unroll
        for (int nt = 0; nt < 4; nt++) {
            int c = n0 + wn + nt * 8 + gc2;
            float bx = 0.f, by = 0.f;
            if (bias) { float2 b2 = *(const float2*)(bias + c); bx = b2.x; by = b2.y; }
            float v00 = acc[mt][nt][0] + bx, v01 = acc[mt][nt][1] + by;
            float v10 = acc[mt][nt][2] + bx, v11 = acc[mt][nt][3] + by;
            if (Cf) {
                *(float2*)(Cf + (size_t)r * ldcf + c)       = make_float2(v00, v01);
                *(float2*)(Cf + (size_t)(r + 8) * ldcf + c) = make_float2(v10, v11);
            }
            if (Chi) {
                bf h00 = __float2bfloat16(v00), h01 = __float2bfloat16(v01);
                bf h10 = __float2bfloat16(v10), h11 = __float2bfloat16(v11);
                __nv_bfloat162 hp0 = __halves2bfloat162(h00, h01);
                __nv_bfloat162 hp1 = __halves2bfloat162(h10, h11);
                *(__nv_bfloat162*)(Chi + (size_t)r * ldch + c)       = hp0;
                *(__nv_bfloat162*)(Chi + (size_t)(r + 8) * ldch + c) = hp1;
                __nv_bfloat162 lp0 = __halves2bfloat162(
                    __float2bfloat16(v00 - __bfloat162float(h00)),
                    __float2bfloat16(v01 - __bfloat162float(h01)));
                __nv_bfloat162 lp1 = __halves2bfloat162(
                    __float2bfloat16(v10 - __bfloat162float(h10)),
                    __float2bfloat16(v11 - __bfloat162float(h11)));
                *(__nv_bfloat162*)(Clo + (size_t)r * ldch + c)       = lp0;
                *(__nv_bfloat162*)(Clo + (size_t)(r + 8) * ldch + c) = lp1;
            }
        }
    }
}

// proj wrapper: dense [ROWS,DD] @ W'[DD,DD]
__global__ __launch_bounds__(256) void hgemm_proj(
    const bf* __restrict__ Ahi, const bf* __restrict__ Alo,
    const bf* __restrict__ Bhi, const bf* __restrict__ Blo,
    const float* __restrict__ bias,
    float* __restrict__ Cf, bf* __restrict__ Chi, bf* __restrict__ Clo)
{
    extern __shared__ char smem[];
    hgemm128_core(smem_u32(smem), Ahi, Alo, DD, Bhi, Blo, DD, bias,
                  Cf, DD, Chi, Clo, DD, DD,
                  blockIdx.y * 128, blockIdx.x * 128);
}

// scores wrapper: per (b,h): attn = qh @ kh^T, K=64, strided slices
__global__ __launch_bounds__(256) void hgemm_scores(
    const bf* __restrict__ qph, const bf* __restrict__ qpl,
    const bf* __restrict__ kph, const bf* __restrict__ kpl,
    float* __restrict__ attn)
{
    extern __shared__ char smem[];
    int bh = blockIdx.z, b = bh >> 4, h = bh & 15;
    size_t off = (size_t)b * CC * DD + h * DHH;
    hgemm128_core(smem_u32(smem), qph + off, qpl + off, DD,
                  kph + off, kpl + off, DD, nullptr,
                  attn + (size_t)bh * CC * CC, CC,
                  nullptr, nullptr, 0, DHH,
                  blockIdx.y * 128, blockIdx.x * 128);
}

// ---------------------------------------------------------------------------
// ctx HMMA: per (b,h): ctx = attn @ vt^T; tile 128x64, K=1024, 2-stage.
// A = attn hi/lo [bh][C][C]; B = vt hi/lo rows [b*C + h*64 .. +64), stride CC.
// 8 warps (4x2), warp tile 32x32. Emits bf16 hi/lo ctx directly.
// ---------------------------------------------------------------------------
#define CSTG 30720
#define CAH 0
#define CAL 10240
#define CBH 20480
#define CBL 25600

__global__ __launch_bounds__(256) void hgemm_ctx(
    const bf* __restrict__ Ah, const bf* __restrict__ Al,
    const bf* __restrict__ Bh, const bf* __restrict__ Bl,
    bf* __restrict__ Chi, bf* __restrict__ Clo)
{
    extern __shared__ char smem[];
    uint32_t sb = smem_u32(smem);
    int bh = blockIdx.z, b = bh >> 4, h = bh & 15;
    const bf* Ahi = Ah + (size_t)bh * CC * CC;
    const bf* Alo = Al + (size_t)bh * CC * CC;
    const bf* Bhi = Bh + (size_t)(b * CC + h * DHH) * CC;
    const bf* Blo = Bl + (size_t)(b * CC + h * DHH) * CC;
    int m0 = blockIdx.y * 128;

    int tid = threadIdx.x, wid = tid >> 5, lane = tid & 31;
    int wm = (wid >> 1) * 32, wn = (wid & 1) * 32;
    float acc[2][4][4];
    #pragma unroll
    for (int i = 0; i < 2; i++)
        #pragma unroll
        for (int j = 0; j < 4; j++)
            #pragma unroll
            for (int q = 0; q < 4; q++) acc[i][j][q] = 0.f;

    int a_row = lane & 15, a_k8 = lane >> 4;
    int b_n = (lane >> 4) * 8 + (lane & 7), b_k8 = (lane >> 3) & 1;
    int r0 = tid >> 2, c0 = tid & 3;

    auto do_load = [&](int kt, int s) {
        uint32_t base = sb + s * CSTG;
        #pragma unroll
        for (int i = 0; i < 2; i++) {
            int row = r0 + i * 64;
            uint32_t so = (uint32_t)(row * GP + c0 * 8) * 2;
            size_t ga = (size_t)(m0 + row) * CC + kt * 32 + c0 * 8;
            CP16(base + CAH + so, Ahi + ga);
            CP16(base + CAL + so, Alo + ga);
        }
        {   // B: 64 rows, one 16B per thread per array
            uint32_t so = (uint32_t)(r0 * GP + c0 * 8) * 2;
            size_t gb = (size_t)r0 * CC + kt * 32 + c0 * 8;
            CP16(base + CBH + so, Bhi + gb);
            CP16(base + CBL + so, Blo + gb);
        }
    };
    auto do_compute = [&](int s) {
        uint32_t base = sb + s * CSTG;
        #pragma unroll
        for (int kk = 0; kk < 32; kk += 16) {
            uint32_t ah[2][4], al[2][4], bh2[2][4], bl2[2][4];
            #pragma unroll
            for (int mt = 0; mt < 2; mt++) {
                uint32_t off = (uint32_t)((wm + mt * 16 + a_row) * GP
                                          + kk + a_k8 * 8) * 2;
                ldmatrix_x4(ah[mt][0], ah[mt][1], ah[mt][2], ah[mt][3],
                            base + CAH + off);
                ldmatrix_x4(al[mt][0], al[mt][1], al[mt][2], al[mt][3],
                            base + CAL + off);
            }
            #pragma unroll
            for (int bt = 0; bt < 2; bt++) {
                uint32_t off = (uint32_t)((wn + bt * 16 + b_n) * GP
                                          + kk + b_k8 * 8) * 2;
                ldmatrix_x4(bh2[bt][0], bh2[bt][1], bh2[bt][2], bh2[bt][3],
                            base + CBH + off);
                ldmatrix_x4(bl2[bt][0], bl2[bt][1], bl2[bt][2], bl2[bt][3],
                            base + CBL + off);
            }
            #pragma unroll
            for (int mt = 0; mt < 2; mt++) {
                #pragma unroll
                for (int nt = 0; nt < 4; nt++) {
                    int bt = nt >> 1, hf = (nt & 1) * 2;
                    mma_bf16(acc[mt][nt], ah[mt], bh2[bt][hf], bh2[bt][hf + 1]);
                    mma_bf16(acc[mt][nt], ah[mt], bl2[bt][hf], bl2[bt][hf + 1]);
                    mma_bf16(acc[mt][nt], al[mt], bh2[bt][hf], bh2[bt][hf + 1]);
                }
            }
        }
    };

    int nch = CC / 32;
    do_load(0, 0); CP_COMMIT();
    for (int kt = 0; kt < nch; kt++) {
        int cur = kt & 1;
        if (kt + 1 < nch) { do_load(kt + 1, cur ^ 1); CP_COMMIT(); CP_WAIT1(); }
        else              { CP_WAIT0(); }
        __syncthreads();
        do_compute(cur);
        __syncthreads();
    }

    int gr = lane >> 2, gc2 = (lane & 3) * 2;
    #pragma unroll
    for (int mt = 0; mt < 2; mt++) {
        int r = m0 + wm + mt * 16 + gr;            // row within C
        size_t grow0 = (size_t)(b * CC + r) * DD;
        size_t grow1 = (size_t)(b * CC + r + 8) * DD;
        #pragma unroll
        for (int nt = 0; nt < 4; nt++) {
            int c = h * DHH + wn + nt * 8 + gc2;   // global col
            float v00 = acc[mt][nt][0], v01 = acc[mt][nt][1];
            float v10 = acc[mt][nt][2], v11 = acc[mt][nt][3];
            bf h00 = __float2bfloat16(v00), h01 = __float2bfloat16(v01);
            bf h10 = __float2bfloat16(v10), h11 = __float2bfloat16(v11);
            *(__nv_bfloat162*)(Chi + grow0 + c) = __halves2bfloat162(h00, h01);
            *(__nv_bfloat162*)(Chi + grow1 + c) = __halves2bfloat162(h10, h11);
            *(__nv_bfloat162*)(Clo + grow0 + c) = __halves2bfloat162(
                __float2bfloat16(v00 - __bfloat162float(h00)),
                __float2bfloat16(v01 - __bfloat162float(h01)));
            *(__nv_bfloat162*)(Clo + grow1 + c) = __halves2bfloat162(
                __float2bfloat16(v10 - __bfloat162float(h10)),
                __float2bfloat16(v11 - __bfloat162float(h11)));
        }
    }
}

// ---------------------------------------------------------------------------
// fp32 -> bf16 hi/lo split (elementwise) -- for q
// ---------------------------------------------------------------------------
__global__ __launch_bounds__(256) void split_kernel(
    const float* __restrict__ x, bf* __restrict__ hi, bf* __restrict__ lo)
{
    int i = blockIdx.x * 256 + threadIdx.x;
    float4 v = ((const float4*)x)[i];
    bf h0 = __float2bfloat16(v.x), h1 = __float2bfloat16(v.y);
    bf h2 = __float2bfloat16(v.z), h3 = __float2bfloat16(v.w);
    union { __nv_bfloat162 b2[2]; uint2 u; } ph, pl;
    ph.b2[0] = __halves2bfloat162(h0, h1); ph.b2[1] = __halves2bfloat162(h2, h3);
    pl.b2[0] = __halves2bfloat162(__float2bfloat16(v.x - __bfloat162float(h0)),
                                  __float2bfloat16(v.y - __bfloat162float(h1)));
    pl.b2[1] = __halves2bfloat162(__float2bfloat16(v.z - __bfloat162float(h2)),
                                  __float2bfloat16(v.w - __bfloat162float(h3)));
    ((uint2*)hi)[i] = ph.u;
    ((uint2*)lo)[i] = pl.u;
}

// W[K,N] -> hiT/loT [N,K] (transposed split)
__global__ void split_wt_kernel(const float* __restrict__ W,
                                bf* __restrict__ hiT, bf* __restrict__ loT)
{
    __shared__ float t[32][33];
    int k0 = blockIdx.y * 32, n0 = blockIdx.x * 32;
    int tx = threadIdx.x, ty = threadIdx.y;   // 32 x 8
    #pragma unroll
    for (int j = 0; j < 4; j++)
        t[ty + j * 8][tx] = W[(size_t)(k0 + ty + j * 8) * DD + n0 + tx];
    __syncthreads();
    #pragma unroll
    for (int j = 0; j < 4; j++) {
        float x = t[tx][ty + j * 8];
        bf h = __float2bfloat16(x);
        size_t o = (size_t)(n0 + ty + j * 8) * DD + k0 + tx;
        hiT[o] = h;
        loT[o] = __float2bfloat16(x - __bfloat162float(h));
    }
}

// vp[b*C + c][n] -> vt[(b*C + n)][c] hi/lo (per-batch transpose split)
__global__ void transpose_split_kernel(const float* __restrict__ vp,
                                       bf* __restrict__ vth, bf* __restrict__ vtl)
{
    __shared__ float t[32][33];
    int b = blockIdx.z;
    int c0 = blockIdx.x * 32, n0 = blockIdx.y * 32;
    int tx = threadIdx.x, ty = threadIdx.y;   // 32 x 8
    #pragma unroll
    for (int j = 0; j < 4; j++)
        t[ty + j * 8][tx] = vp[(size_t)(b * CC + c0 + ty + j * 8) * DD + n0 + tx];
    __syncthreads();
    #pragma unroll
    for (int j = 0; j < 4; j++) {
        float x = t[tx][ty + j * 8];
        bf h = __float2bfloat16(x);
        size_t o = (size_t)(b * CC + n0 + ty + j * 8) * CC + c0 + tx;
        vth[o] = h;
        vtl[o] = __float2bfloat16(x - __bfloat162float(h));
    }
}

// ---------------------------------------------------------------------------
// LayerNorm -> bf16 hi/lo directly
// ---------------------------------------------------------------------------
__global__ __launch_bounds__(256) void ln_bf16_kernel(
    const float* __restrict__ x, const float* __restrict__ gam,
    const float* __restrict__ bet, bf* __restrict__ oh, bf* __restrict__ ol)
{
    int row = blockIdx.x;
    int tid = threadIdx.x;
    const float4 v = ((const float4*)(x + (size_t)row * DD))[tid];
    float s  = v.x + v.y + v.z + v.w;
    float ss = v.x*v.x + v.y*v.y + v.z*v.z + v.w*v.w;
    #pragma unroll
    for (int o = 16; o > 0; o >>= 1) {
        s  += __shfl_xor_sync(0xFFFFFFFFu, s, o);
        ss += __shfl_xor_sync(0xFFFFFFFFu, ss, o);
    }
    __shared__ float sh_s[8], sh_ss[8];
    __shared__ float sh_m, sh_r;
    int w = tid >> 5, l = tid & 31;
    if (l == 0) { sh_s[w] = s; sh_ss[w] = ss; }
    __syncthreads();
    if (tid == 0) {
        float S = 0.f, SS = 0.f;
        #pragma unroll
        for (int i = 0; i < 8; i++) { S += sh_s[i]; SS += sh_ss[i]; }
        float m = S * (1.0f / DD);
        sh_m = m;
        sh_r = rsqrtf(SS * (1.0f / DD) - m * m + 1e-5f);
    }
    __syncthreads();
    float m = sh_m, r = sh_r;
    const float4 g4 = ((const float4*)gam)[tid];
    const float4 b4 = ((const float4*)bet)[tid];
    float y0 = (v.x - m) * r * g4.x + b4.x;
    float y1 = (v.y - m) * r * g4.y + b4.y;
    float y2 = (v.z - m) * r * g4.z + b4.z;
    float y3 = (v.w - m) * r * g4.w + b4.w;
    bf h0 = __float2bfloat16(y0), h1 = __float2bfloat16(y1);
    bf h2 = __float2bfloat16(y2), h3 = __float2bfloat16(y3);
    union { __nv_bfloat162 b2[2]; uint2 u; } ph, pl;
    ph.b2[0] = __halves2bfloat162(h0, h1); ph.b2[1] = __halves2bfloat162(h2, h3);
    pl.b2[0] = __halves2bfloat162(__float2bfloat16(y0 - __bfloat162float(h0)),
                                  __float2bfloat16(y1 - __bfloat162float(h1)));
    pl.b2[1] = __halves2bfloat162(__float2bfloat16(y2 - __bfloat162float(h2)),
                                  __float2bfloat16(y3 - __bfloat162float(h3)));
    ((uint2*)(oh + (size_t)row * DD))[tid] = ph.u;
    ((uint2*)(ol + (size_t)row * DD))[tid] = pl.u;
}

// ---------------------------------------------------------------------------
// GELU*scale + softmax; writes fp32 (optional) + bf16 hi/lo
// ---------------------------------------------------------------------------
__global__ __launch_bounds__(256) void softmax_kernel(
    const float* __restrict__ in, float* __restrict__ outf,
    bf* __restrict__ oh, bf* __restrict__ ol, int write_f)
{
    size_t row = blockIdx.x;
    const float* r = in + row * (size_t)CC;
    int tid = threadIdx.x;
    float4 v = ((const float4*)r)[tid];
    const float scale = 0.125f;
    const float inv_sqrt2 = 0.70710678118654752f;
    float t0 = 0.5f * v.x * (1.0f + erff(v.x * inv_sqrt2)) * scale;
    float t1 = 0.5f * v.y * (1.0f + erff(v.y * inv_sqrt2)) * scale;
    float t2 = 0.5f * v.z * (1.0f + erff(v.z * inv_sqrt2)) * scale;
    float t3 = 0.5f * v.w * (1.0f + erff(v.w * inv_sqrt2)) * scale;

    float mx = fmaxf(fmaxf(t0, t1), fmaxf(t2, t3));
    #pragma unroll
    for (int o = 16; o > 0; o >>= 1)
        mx = fmaxf(mx, __shfl_xor_sync(0xFFFFFFFFu, mx, o));
    __shared__ float shm[8];
    __shared__ float shv;
    int w = tid >> 5, l = tid & 31;
    if (l == 0) shm[w] = mx;
    __syncthreads();
    if (tid == 0) {
        float M = shm[0];
        #pragma unroll
        for (int i = 1; i < 8; i++) M = fmaxf(M, shm[i]);
        shv = M;
    }
    __syncthreads();
    float M = shv;
    float e0 = __expf(t0 - M), e1 = __expf(t1 - M);
    float e2 = __expf(t2 - M), e3 = __expf(t3 - M);
    float s = e0 + e1 + e2 + e3;
    #pragma unroll
    for (int o = 16; o > 0; o >>= 1)
        s += __shfl_xor_sync(0xFFFFFFFFu, s, o);
    if (l == 0) shm[w] = s;
    __syncthreads();
    if (tid == 0) {
        float S = 0.f;
        #pragma unroll
        for (int i = 0; i < 8; i++) S += shm[i];
        shv = 1.0f / S;
    }
    __syncthreads();
    float inv = shv;
    float a0 = e0 * inv, a1 = e1 * inv, a2 = e2 * inv, a3 = e3 * inv;
    if (write_f) {
        float4 o4; o4.x = a0; o4.y = a1; o4.z = a2; o4.w = a3;
        ((float4*)(outf + row * (size_t)CC))[tid] = o4;
    }
    bf h0 = __float2bfloat16(a0), h1 = __float2bfloat16(a1);
    bf h2 = __float2bfloat16(a2), h3 = __float2bfloat16(a3);
    union { __nv_bfloat162 b2[2]; uint2 u; } ph, pl;
    ph.b2[0] = __halves2bfloat162(h0, h1); ph.b2[1] = __halves2bfloat162(h2, h3);
    pl.b2[0] = __halves2bfloat162(__float2bfloat16(a0 - __bfloat162float(h0)),
                                  __float2bfloat16(a1 - __bfloat162float(h1)));
    pl.b2[1] = __halves2bfloat162(__float2bfloat16(a2 - __bfloat162float(h2)),
                                  __float2bfloat16(a3 - __bfloat162float(h3)));
    ((uint2*)(oh + row * (size_t)CC))[tid] = ph.u;
    ((uint2*)(ol + row * (size_t)CC))[tid] = pl.u;
}

// ---------------------------------------------------------------------------
// L2 normalize rows
// ---------------------------------------------------------------------------
__global__ __launch_bounds__(256) void l2norm_kernel(
    const float* __restrict__ x, float* __restrict__ y)
{
    int row = blockIdx.x;
    int tid = threadIdx.x;
    const float4 v = ((const float4*)(x + (size_t)row * DD))[tid];
    float ss = v.x*v.x + v.y*v.y + v.z*v.z + v.w*v.w;
    #pragma unroll
    for (int o = 16; o > 0; o >>= 1)
        ss += __shfl_xor_sync(0xFFFFFFFFu, ss, o);
    __shared__ float sh[8];
    __shared__ float shinv;
    int w = tid >> 5, l = tid & 31;
    if (l == 0) sh[w] = ss;
    __syncthreads();
    if (tid == 0) {
        float S = 0.f;
        #pragma unroll
        for (int i = 0; i < 8; i++) S += sh[i];
        shinv = 1.0f / fmaxf(sqrtf(S), 1e-12f);
    }
    __syncthreads();
    float inv = shinv;
    float4 o;
    o.x = v.x * inv; o.y = v.y * inv; o.z = v.z * inv; o.w = v.w * inv;
    ((float4*)(y + (size_t)row * DD))[tid] = o;
}

// ---------------------------------------------------------------------------
extern "C" void kernel_launch(void* const* d_in, const int* in_sizes, int n_in,
                              void* d_out, int out_size)
{
    const float* q      = (const float*)d_in[0];
    const float* k      = (const float*)d_in[1];
    const float* v      = (const float*)d_in[2];
    const float* ln_k_g = (const float*)d_in[3];
    const float* ln_k_b = (const float*)d_in[4];
    const float* ln_v_g = (const float*)d_in[5];
    const float* ln_v_b = (const float*)d_in[6];
    const float* Wq     = (const float*)d_in[7];
    const float* bq     = (const float*)d_in[8];
    const float* Wk     = (const float*)d_in[9];
    const float* bk     = (const float*)d_in[10];
    const float* Wv     = (const float*)d_in[11];
    const float* bv     = (const float*)d_in[12];
    const float* Wo     = (const float*)d_in[13];
    const float* bo     = (const float*)d_in[14];

    float* out = (float*)d_out;

    float *vp, *proj, *attn_scr;
    bf *qh, *ql, *knh, *knl, *vnh, *vnl, *qph, *qpl, *kph, *kpl;
    bf *vth, *vtl, *cxh, *cxl, *bhi, *blo, *ath, *atl;
    cudaGetSymbolAddress((void**)&vp,   g_vp);
    cudaGetSymbolAddress((void**)&proj, g_proj);
    cudaGetSymbolAddress((void**)&attn_scr, g_attn_scratch);
    cudaGetSymbolAddress((void**)&qh,  g_qh);  cudaGetSymbolAddress((void**)&ql,  g_ql);
    cudaGetSymbolAddress((void**)&knh, g_knh); cudaGetSymbolAddress((void**)&knl, g_knl);
    cudaGetSymbolAddress((void**)&vnh, g_vnh); cudaGetSymbolAddress((void**)&vnl, g_vnl);
    cudaGetSymbolAddress((void**)&qph, g_qph); cudaGetSymbolAddress((void**)&qpl, g_qpl);
    cudaGetSymbolAddress((void**)&kph, g_kph); cudaGetSymbolAddress((void**)&kpl, g_kpl);
    cudaGetSymbolAddress((void**)&vth, g_vth); cudaGetSymbolAddress((void**)&vtl, g_vtl);
    cudaGetSymbolAddress((void**)&cxh, g_cxh); cudaGetSymbolAddress((void**)&cxl, g_cxl);
    cudaGetSymbolAddress((void**)&bhi, g_bhi); cudaGetSymbolAddress((void**)&blo, g_blo);
    cudaGetSymbolAddress((void**)&ath, g_ath); cudaGetSymbolAddress((void**)&atl, g_atl);

    int attn_in_out = (out_size >= (int)(ELEMS + ATTN_ELEMS));
    float* attn = attn_in_out ? (out + (size_t)ELEMS) : attn_scr;

    cudaFuncSetAttribute(hgemm_proj,
        cudaFuncAttributeMaxDynamicSharedMemorySize, 2 * STG);
    cudaFuncSetAttribute(hgemm_scores,
        cudaFuncAttributeMaxDynamicSharedMemorySize, 2 * STG);
    cudaFuncSetAttribute(hgemm_ctx,
        cudaFuncAttributeMaxDynamicSharedMemorySize, 2 * CSTG);

    dim3 gmm(DD / 128, ROWS / 128);      // (8, 32)
    dim3 gwt(DD / 32, DD / 32);          // (32, 32)
    dim3 bwt(32, 8);
    int splitBlocks = ELEMS / 4 / 256;

    // 1) LayerNorm k, v -> bf16 hi/lo; split q
    ln_bf16_kernel<<<ROWS, 256>>>(k, ln_k_g, ln_k_b, knh, knl);
    ln_bf16_kernel<<<ROWS, 256>>>(v, ln_v_g, ln_v_b, vnh, vnl);
    split_kernel<<<splitBlocks, 256>>>(q, qh, ql);

    // 2) projections (HMMA, 2-stage cp.async)
    split_wt_kernel<<<gwt, bwt>>>(Wq, bhi, blo);
    hgemm_proj<<<gmm, 256, 2 * STG>>>(qh, ql, bhi, blo, bq, nullptr, qph, qpl);
    split_wt_kernel<<<gwt, bwt>>>(Wk, bhi, blo);
    hgemm_proj<<<gmm, 256, 2 * STG>>>(knh, knl, bhi, blo, bk, nullptr, kph, kpl);
    split_wt_kernel<<<gwt, bwt>>>(Wv, bhi, blo);
    hgemm_proj<<<gmm, 256, 2 * STG>>>(vnh, vnl, bhi, blo, bv, vp, nullptr, nullptr);

    // 3) vp -> per-batch transposed bf16 hi/lo
    transpose_split_kernel<<<dim3(32, 32, BB), bwt>>>(vp, vth, vtl);

    // 4) scores (HMMA) -> attn fp32
    hgemm_scores<<<dim3(8, 8, BB * HH), 256, 2 * STG>>>(qph, qpl, kph, kpl, attn);

    // 5) softmax -> attn fp32 (if output) + bf16 hi/lo
    softmax_kernel<<<BB * HH * CC, 256>>>(attn, attn, ath, atl, attn_in_out);

    // 6) ctx (HMMA) -> bf16 hi/lo directly
    hgemm_ctx<<<dim3(1, 8, BB * HH), 256, 2 * CSTG>>>(ath, atl, vth, vtl, cxh, cxl);

    // 7) output projection + L2 normalize
    split_wt_kernel<<<gwt, bwt>>>(Wo, bhi, blo);
    hgemm_proj<<<gmm, 256, 2 * STG>>>(cxh, cxl, bhi, blo, bo, proj, nullptr, nullptr);
    l2norm_kernel<<<ROWS, 256>>>(proj, out);
}